// round 13
// baseline (speedup 1.0000x reference)
#include <cuda_runtime.h>
#include <cuda_bf16.h>
#include <cstdint>

// ===========================================================================
// SparseMotionEncoder — round 13: no global atomics.
// Tap-major rulebook HMMA bf16x3 GEMMs write per-pair results to a scratch
// buffer with plain stores; a per-output CSR gather-reduce sums contributions
// (+bias +relu). LTS atomic-ALU bottleneck removed.
// ===========================================================================

#define NVOX 50000
#define NPMAX 420000          // pair cap (actual ~284K at 19% occupancy)

__device__ float g_corr1[NVOX * 256];
__device__ float g_f1[NVOX * 128];
__device__ float g_cat[NVOX * 256];

__device__ float g_scrA[(size_t)NPMAX * 192];   // c2 scratch; reused by cat (stride 128)
__device__ float g_scrB[(size_t)NPMAX * 64];    // f2 scratch

__device__ int  g_cnt3[27];
__device__ int  g_tapbase[27];
__device__ int2 g_list3[27 * NVOX];     // (in_idx, out_idx) per tap
__device__ int  g_nitems;
__device__ int  g_items[10560];         // packed: tap | (mtile << 5)
__device__ int  g_ccnt[NVOX];
__device__ int  g_csr[NVOX * 28];       // scratch-row positions per output

// Transposed, split weights: [KK][COUTPAD][CINPAD] bf16, zero padded.
__device__ __nv_bfloat16 gW_c1_hi[1 * 256 * 352], gW_c1_lo[1 * 256 * 352];
__device__ __nv_bfloat16 gW_c2_hi[27 * 192 * 256], gW_c2_lo[27 * 192 * 256];
__device__ __nv_bfloat16 gW_f2_hi[27 * 64 * 128],  gW_f2_lo[27 * 64 * 128];
__device__ __nv_bfloat16 gW_ct_hi[27 * 128 * 256], gW_ct_lo[27 * 128 * 256];

__device__ __forceinline__ uint32_t pkbf(float a, float b) {
    __nv_bfloat162 t = __floats2bfloat162_rn(a, b);
    return *reinterpret_cast<uint32_t*>(&t);
}
__device__ __forceinline__ void mma16816(float* c, const uint32_t* a,
                                         const uint32_t* b) {
    asm volatile(
        "mma.sync.aligned.m16n8k16.row.col.f32.bf16.bf16.f32 "
        "{%0,%1,%2,%3}, {%4,%5,%6,%7}, {%8,%9}, {%0,%1,%2,%3};"
        : "+f"(c[0]), "+f"(c[1]), "+f"(c[2]), "+f"(c[3])
        : "r"(a[0]), "r"(a[1]), "r"(a[2]), "r"(a[3]), "r"(b[0]), "r"(b[1]));
}
__device__ __forceinline__ void ldsm4(uint32_t* r, uint32_t addr) {
    asm volatile(
        "ldmatrix.sync.aligned.m8n8.x4.shared.b16 {%0,%1,%2,%3}, [%4];"
        : "=r"(r[0]), "=r"(r[1]), "=r"(r[2]), "=r"(r[3]) : "r"(addr));
}
__device__ __forceinline__ void cpasync16(uint32_t dst, const void* src) {
    asm volatile("cp.async.cg.shared.global [%0], [%1], 16;" :: "r"(dst), "l"(src));
}
#define CP_COMMIT() asm volatile("cp.async.commit_group;" ::: "memory")
#define CP_WAIT0()  asm volatile("cp.async.wait_group 0;" ::: "memory")

// ---------------------------------------------------------------------------
template <int KK, int CIN, int COUT, int CINPAD, int COUTPAD>
__global__ void prep_w(const float* __restrict__ W,
                       __nv_bfloat16* __restrict__ hi,
                       __nv_bfloat16* __restrict__ lo)
{
    long tid = (long)blockIdx.x * blockDim.x + threadIdx.x;
    const long total = (long)KK * COUTPAD * CINPAD;
    if (tid >= total) return;
    int c = tid % CINPAD;
    long r = tid / CINPAD;
    int n = r % COUTPAD;
    int k = r / COUTPAD;
    float x = (c < CIN && n < COUT) ? W[((size_t)k * CIN + c) * COUT + n] : 0.f;
    __nv_bfloat16 h = __float2bfloat16(x);
    hi[tid] = h;
    lo[tid] = __float2bfloat16(x - __bfloat162float(h));
}

// ---------------------------------------------------------------------------
__global__ void zero_cnt()
{
    if (threadIdx.x < 27) g_cnt3[threadIdx.x] = 0;
    if (threadIdx.x == 31) g_nitems = 0;
}

__global__ void zero_ccnt(int N)
{
    int i = blockIdx.x * 256 + threadIdx.x;
    if (i < N) g_ccnt[i] = 0;
}

__global__ void build_list(const int* __restrict__ nbr, int N)
{
    const int k = blockIdx.y;
    const int n = blockIdx.x * 256 + threadIdx.x;
    const int lane = threadIdx.x & 31;
    int idx = -1;
    if (n < N) idx = nbr[(size_t)k * N + n];
    const bool v = idx >= 0;
    unsigned m = __ballot_sync(0xffffffffu, v);
    if (!m) return;
    int leader = __ffs(m) - 1;
    int base = 0;
    if (lane == leader) base = atomicAdd(&g_cnt3[k], __popc(m));
    base = __shfl_sync(0xffffffffu, base, leader);
    if (v) {
        int pos = base + __popc(m & ((1u << lane) - 1u));
        g_list3[(size_t)k * NVOX + pos] = make_int2(idx, n);
    }
}

__global__ void sched()
{
    if (threadIdx.x == 0) {
        int base = 0;
        for (int k = 0; k < 27; ++k) {
            g_tapbase[k] = base;
            base += g_cnt3[k];
        }
    }
    __syncthreads();
    int k = threadIdx.x;
    if (k < 27) {
        int tiles = (g_cnt3[k] + 127) >> 7;
        int base = atomicAdd(&g_nitems, tiles);
        for (int i = 0; i < tiles; ++i)
            g_items[base + i] = k | (i << 5);
    }
}

__global__ void build_csr(int N)
{
    const int k = blockIdx.y;
    const int pos = blockIdx.x * 256 + threadIdx.x;
    if (pos >= g_cnt3[k]) return;
    const int n = g_list3[(size_t)k * NVOX + pos].y;
    const int slot = atomicAdd(&g_ccnt[n], 1);
    g_csr[n * 28 + slot] = g_tapbase[k] + pos;
}

// ---------------------------------------------------------------------------
// Gather-reduce: cat[n][0:192] = relu(bc2 + sum scrA), [192:256] = relu(bf2+sum scrB)
// ---------------------------------------------------------------------------
__global__ void __launch_bounds__(256)
reduce_cat(const float* __restrict__ b0, const float* __restrict__ b1, int N)
{
    const int warp = threadIdx.x >> 5, lane = threadIdx.x & 31;
    const int n = blockIdx.x * 8 + warp;
    if (n >= N) return;
    const int cnt = g_ccnt[n];
    float a[6] = {0.f, 0.f, 0.f, 0.f, 0.f, 0.f};
    float b[2] = {0.f, 0.f};
    for (int s = 0; s < cnt; ++s) {
        const int p = g_csr[n * 28 + s];
        const float* rA = g_scrA + (size_t)p * 192;
        const float* rB = g_scrB + (size_t)p * 64;
#pragma unroll
        for (int j = 0; j < 6; ++j) a[j] += rA[lane + j * 32];
#pragma unroll
        for (int j = 0; j < 2; ++j) b[j] += rB[lane + j * 32];
    }
    float* dst = g_cat + (size_t)n * 256;
#pragma unroll
    for (int j = 0; j < 6; ++j)
        dst[lane + j * 32] = fmaxf(a[j] + b0[lane + j * 32], 0.f);
#pragma unroll
    for (int j = 0; j < 2; ++j)
        dst[192 + lane + j * 32] = fmaxf(b[j] + b1[lane + j * 32], 0.f);
}

// out[n][0:120] = relu(bcat + sum scrA(stride 128))
__global__ void __launch_bounds__(256)
reduce_out(const float* __restrict__ bias, float* __restrict__ out, int N)
{
    const int warp = threadIdx.x >> 5, lane = threadIdx.x & 31;
    const int n = blockIdx.x * 8 + warp;
    if (n >= N) return;
    const int cnt = g_ccnt[n];
    float a[4] = {0.f, 0.f, 0.f, 0.f};
    for (int s = 0; s < cnt; ++s) {
        const int p = g_csr[n * 28 + s];
        const float* rA = g_scrA + (size_t)p * 128;
#pragma unroll
        for (int j = 0; j < 4; ++j) {
            const int c = lane + j * 32;
            if (c < 120) a[j] += rA[c];
        }
    }
#pragma unroll
    for (int j = 0; j < 4; ++j) {
        const int c = lane + j * 32;
        if (c < 120)
            out[(size_t)n * 128 + c] = fmaxf(a[j] + bias[c], 0.f);
    }
}

// ---------------------------------------------------------------------------
// Dense pipelined HMMA gather-GEMM (identity rows) — c1 only.
// ---------------------------------------------------------------------------
template <int KK, int CIN, int CINPAD, int NT>
__global__ void __launch_bounds__(256, 2)
tmma(const float* __restrict__ feat, int fstride,
     const __nv_bfloat16* __restrict__ Whi, const __nv_bfloat16* __restrict__ Wlo,
     int COUTPAD, const float* __restrict__ bias, float* __restrict__ out,
     int ostride, int ocol, int COUT, int N)
{
    constexpr bool TAIL = (CIN % 32) != 0;
    constexpr int CH = CINPAD / 32;
    constexpr int ITERS = KK * CH;
    constexpr int WN = NT / 2;
    constexpr int J  = NT / 16;
    constexpr int JP = J / 2;
    constexpr int BQ = (NT * 8) / 256;
    constexpr uint32_t AB = 10240;
    constexpr uint32_t BB = NT * 80;

    extern __shared__ char dyn[];
    const uint32_t sb = (uint32_t)__cvta_generic_to_shared(dyn);

    const int t = threadIdx.x, lane = t & 31, w = t >> 5;
    const int wm = w >> 1, wn = w & 1;
    const int g = lane >> 2, tg = lane & 3;
    const int row0 = blockIdx.x * 128;
    const int n0 = blockIdx.y * NT;

    float acc[2][J][4];
#pragma unroll
    for (int i = 0; i < 2; ++i)
#pragma unroll
        for (int j = 0; j < J; ++j)
#pragma unroll
            for (int q = 0; q < 4; ++q) acc[i][j][q] = 0.f;

    const int gr = t >> 1;
    const int gcb = (t & 1) * 16;
    const int grow = row0 + gr;

    float4 va[4];

    auto gatherA = [&](int it) {
        const int cc = it % CH;
        const float* frow = (grow < N) ? feat + (size_t)grow * fstride : nullptr;
        const int c0 = cc * 32;
#pragma unroll
        for (int i = 0; i < 4; ++i) {
            const int gcol = c0 + gcb + i * 4;
            float4 v = make_float4(0.f, 0.f, 0.f, 0.f);
            if (frow) {
                if (!TAIL || gcol + 3 < CIN) {
                    v = *reinterpret_cast<const float4*>(frow + gcol);
                } else {
                    float tmp[4] = {0.f, 0.f, 0.f, 0.f};
#pragma unroll
                    for (int jj = 0; jj < 4; ++jj)
                        if (gcol + jj < CIN) tmp[jj] = frow[gcol + jj];
                    v = make_float4(tmp[0], tmp[1], tmp[2], tmp[3]);
                }
            }
            va[i] = v;
        }
    };

    auto storeA = [&](int stage) {
        char* base_h = dyn + (stage * 2 + 0) * AB;
        char* base_l = dyn + (stage * 2 + 1) * AB;
        const int roff = gr * 80;
#pragma unroll
        for (int i = 0; i < 4; ++i) {
            float4 v = va[i];
            float hx = __bfloat162float(__float2bfloat16(v.x));
            float hy = __bfloat162float(__float2bfloat16(v.y));
            float hz = __bfloat162float(__float2bfloat16(v.z));
            float hw = __bfloat162float(__float2bfloat16(v.w));
            uint2 uh = make_uint2(pkbf(hx, hy), pkbf(hz, hw));
            uint2 ul = make_uint2(pkbf(v.x - hx, v.y - hy),
                                  pkbf(v.z - hz, v.w - hw));
            const int boff = roff + (gcb + i * 4) * 2;
            *reinterpret_cast<uint2*>(base_h + boff) = uh;
            *reinterpret_cast<uint2*>(base_l + boff) = ul;
        }
    };

    auto issueB = [&](int it, int stage) {
        const int k = it / CH, cc = it % CH;
        const size_t base = ((size_t)k * COUTPAD + n0) * CINPAD + cc * 32;
#pragma unroll
        for (int q = 0; q < BQ; ++q) {
            const int e = t + q * 256;
            const int plane = e / (NT * 4);
            const int re = e - plane * (NT * 4);
            const int row = re >> 2, seg = re & 3;
            const __nv_bfloat16* src =
                (plane ? Wlo : Whi) + base + (size_t)row * CINPAD + seg * 8;
            const uint32_t dst =
                sb + 4 * AB + (uint32_t)(stage * 2 + plane) * BB + row * 80 + seg * 16;
            cpasync16(dst, src);
        }
    };

    gatherA(0);
    issueB(0, 0);
    CP_COMMIT();
    storeA(0);
    CP_WAIT0();
    __syncthreads();

    const int local = lane & 7, grp = lane >> 3;
    const int arow = (grp & 1) * 8 + local;
    const int abyt = (grp >> 1) * 16;
    const int nloc = (grp >> 1) * 8 + local;
    const int bbyt = (grp & 1) * 16;

#pragma unroll 1
    for (int it = 0; it < ITERS; ++it) {
        const int cur = it & 1, nxt = cur ^ 1;
        const bool more = (it + 1 < ITERS);
        if (more) {
            gatherA(it + 1);
            issueB(it + 1, nxt);
            CP_COMMIT();
        }
        const uint32_t aH = sb + (uint32_t)(cur * 2 + 0) * AB;
        const uint32_t aL = sb + (uint32_t)(cur * 2 + 1) * AB;
        const uint32_t bH = sb + 4 * AB + (uint32_t)(cur * 2 + 0) * BB;
        const uint32_t bL = sb + 4 * AB + (uint32_t)(cur * 2 + 1) * BB;
#pragma unroll
        for (int ks = 0; ks < 2; ++ks) {
            uint32_t Ah[2][4], Al[2][4];
#pragma unroll
            for (int i = 0; i < 2; ++i) {
                const uint32_t ao =
                    (uint32_t)((wm * 32 + i * 16 + arow) * 80 + ks * 32 + abyt);
                ldsm4(Ah[i], aH + ao);
                ldsm4(Al[i], aL + ao);
            }
#pragma unroll
            for (int jp = 0; jp < JP; ++jp) {
                const uint32_t bo =
                    (uint32_t)((wn * WN + jp * 16 + nloc) * 80 + ks * 32 + bbyt);
                uint32_t Bh[4], Bl[4];
                ldsm4(Bh, bH + bo);
                ldsm4(Bl, bL + bo);
#pragma unroll
                for (int i = 0; i < 2; ++i) {
                    mma16816(acc[i][2 * jp],     Ah[i], Bh);
                    mma16816(acc[i][2 * jp],     Al[i], Bh);
                    mma16816(acc[i][2 * jp],     Ah[i], Bl);
                    mma16816(acc[i][2 * jp + 1], Ah[i], Bh + 2);
                    mma16816(acc[i][2 * jp + 1], Al[i], Bh + 2);
                    mma16816(acc[i][2 * jp + 1], Ah[i], Bl + 2);
                }
            }
        }
        if (more) {
            storeA(nxt);
            CP_WAIT0();
        }
        __syncthreads();
    }

#pragma unroll
    for (int j = 0; j < J; ++j) {
        const int col = n0 + wn * WN + j * 8 + tg * 2;
        if (col >= COUT) continue;
        const float2 bv = *reinterpret_cast<const float2*>(bias + col);
#pragma unroll
        for (int i = 0; i < 2; ++i) {
            const int r1 = row0 + wm * 32 + i * 16 + g;
            if (r1 < N) {
                float2 o = make_float2(fmaxf(acc[i][j][0] + bv.x, 0.f),
                                       fmaxf(acc[i][j][1] + bv.y, 0.f));
                *reinterpret_cast<float2*>(out + (size_t)r1 * ostride + ocol + col) = o;
            }
            const int r2 = r1 + 8;
            if (r2 < N) {
                float2 o = make_float2(fmaxf(acc[i][j][2] + bv.x, 0.f),
                                       fmaxf(acc[i][j][3] + bv.y, 0.f));
                *reinterpret_cast<float2*>(out + (size_t)r2 * ostride + ocol + col) = o;
            }
        }
    }
}

// ---------------------------------------------------------------------------
// Persistent per-tap rulebook HMMA GEMM -> per-pair scratch (plain stores).
// ---------------------------------------------------------------------------
template <int CIN, int CINPAD, int NT, int NYT>
__global__ void __launch_bounds__(256, 2)
tap_mma_p(const float* __restrict__ feat, int fstride,
          const __nv_bfloat16* __restrict__ Whi, const __nv_bfloat16* __restrict__ Wlo,
          int COUTPAD, float* __restrict__ scr, int SSTR, int COUT)
{
    constexpr int CH = CINPAD / 32;
    constexpr int WN = NT / 2;
    constexpr int J  = NT / 16;
    constexpr int JP = J / 2;
    constexpr int BQ = (NT * 8) / 256;
    constexpr uint32_t AB = 10240;
    constexpr uint32_t BB = NT * 80;
    constexpr int RSF = NT + 4;
    constexpr int NQ = NT / 4;

    __shared__ int sIn[128];
    extern __shared__ char dyn[];
    const uint32_t sb = (uint32_t)__cvta_generic_to_shared(dyn);
    float* sAcc = reinterpret_cast<float*>(dyn);

    const int t = threadIdx.x, lane = t & 31, w = t >> 5;
    const int wm = w >> 1, wn = w & 1;
    const int g = lane >> 2, tg = lane & 3;
    const int gr = t >> 1;
    const int gcb = (t & 1) * 16;
    const int local = lane & 7, grp = lane >> 3;
    const int arow = (grp & 1) * 8 + local;
    const int abyt = (grp >> 1) * 16;
    const int nloc = (grp >> 1) * 8 + local;
    const int bbyt = (grp & 1) * 16;

    const int nwork = g_nitems * NYT;

    for (int wk = blockIdx.x; wk < nwork; wk += gridDim.x) {
        const int item = (NYT == 1) ? wk : (wk >> 1);
        const int y    = (NYT == 1) ? 0  : (wk & 1);
        const int packed = g_items[item];
        const int tap = packed & 31;
        const int m0 = (packed >> 5) << 7;
        const int cn = g_cnt3[tap];
        const int sbase = g_tapbase[tap];
        const int n0 = y * NT;

        __syncthreads();
        if (t < 128) {
            const int m = m0 + t;
            sIn[t] = (m < cn) ? g_list3[(size_t)tap * NVOX + m].x : -1;
        }
        __syncthreads();

        float acc[2][J][4];
#pragma unroll
        for (int i = 0; i < 2; ++i)
#pragma unroll
            for (int j = 0; j < J; ++j)
#pragma unroll
                for (int q = 0; q < 4; ++q) acc[i][j][q] = 0.f;

        const int gin = sIn[gr];
        const float* frow = (gin >= 0) ? feat + (size_t)gin * fstride : nullptr;

        float4 va[4];
        auto gatherA = [&](int it) {
            const int c0 = it * 32;
#pragma unroll
            for (int i = 0; i < 4; ++i) {
                float4 v = make_float4(0.f, 0.f, 0.f, 0.f);
                if (frow) v = *reinterpret_cast<const float4*>(frow + c0 + gcb + i * 4);
                va[i] = v;
            }
        };
        auto storeA = [&](int stage) {
            char* base_h = dyn + (stage * 2 + 0) * AB;
            char* base_l = dyn + (stage * 2 + 1) * AB;
            const int roff = gr * 80;
#pragma unroll
            for (int i = 0; i < 4; ++i) {
                float4 v = va[i];
                float hx = __bfloat162float(__float2bfloat16(v.x));
                float hy = __bfloat162float(__float2bfloat16(v.y));
                float hz = __bfloat162float(__float2bfloat16(v.z));
                float hw = __bfloat162float(__float2bfloat16(v.w));
                uint2 uh = make_uint2(pkbf(hx, hy), pkbf(hz, hw));
                uint2 ul = make_uint2(pkbf(v.x - hx, v.y - hy),
                                      pkbf(v.z - hz, v.w - hw));
                const int boff = roff + (gcb + i * 4) * 2;
                *reinterpret_cast<uint2*>(base_h + boff) = uh;
                *reinterpret_cast<uint2*>(base_l + boff) = ul;
            }
        };
        auto issueB = [&](int it, int stage) {
            const size_t base = ((size_t)tap * COUTPAD + n0) * CINPAD + it * 32;
#pragma unroll
            for (int q = 0; q < BQ; ++q) {
                const int e = t + q * 256;
                const int plane = e / (NT * 4);
                const int re = e - plane * (NT * 4);
                const int row = re >> 2, seg = re & 3;
                const __nv_bfloat16* src =
                    (plane ? Wlo : Whi) + base + (size_t)row * CINPAD + seg * 8;
                const uint32_t dst =
                    sb + 4 * AB + (uint32_t)(stage * 2 + plane) * BB + row * 80 + seg * 16;
                cpasync16(dst, src);
            }
        };

        gatherA(0);
        issueB(0, 0);
        CP_COMMIT();
        storeA(0);
        CP_WAIT0();
        __syncthreads();

#pragma unroll 1
        for (int it = 0; it < CH; ++it) {
            const int cur = it & 1, nxt = cur ^ 1;
            const bool more = (it + 1 < CH);
            if (more) {
                gatherA(it + 1);
                issueB(it + 1, nxt);
                CP_COMMIT();
            }
            const uint32_t aH = sb + (uint32_t)(cur * 2 + 0) * AB;
            const uint32_t aL = sb + (uint32_t)(cur * 2 + 1) * AB;
            const uint32_t bH = sb + 4 * AB + (uint32_t)(cur * 2 + 0) * BB;
            const uint32_t bL = sb + 4 * AB + (uint32_t)(cur * 2 + 1) * BB;
#pragma unroll
            for (int ks = 0; ks < 2; ++ks) {
                uint32_t Ah[2][4], Al[2][4];
#pragma unroll
                for (int i = 0; i < 2; ++i) {
                    const uint32_t ao =
                        (uint32_t)((wm * 32 + i * 16 + arow) * 80 + ks * 32 + abyt);
                    ldsm4(Ah[i], aH + ao);
                    ldsm4(Al[i], aL + ao);
                }
#pragma unroll
                for (int jp = 0; jp < JP; ++jp) {
                    const uint32_t bo =
                        (uint32_t)((wn * WN + jp * 16 + nloc) * 80 + ks * 32 + bbyt);
                    uint32_t Bh[4], Bl[4];
                    ldsm4(Bh, bH + bo);
                    ldsm4(Bl, bL + bo);
#pragma unroll
                    for (int i = 0; i < 2; ++i) {
                        mma16816(acc[i][2 * jp],     Ah[i], Bh);
                        mma16816(acc[i][2 * jp],     Al[i], Bh);
                        mma16816(acc[i][2 * jp],     Ah[i], Bl);
                        mma16816(acc[i][2 * jp + 1], Ah[i], Bh + 2);
                        mma16816(acc[i][2 * jp + 1], Al[i], Bh + 2);
                        mma16816(acc[i][2 * jp + 1], Ah[i], Bl + 2);
                    }
                }
            }
            if (more) {
                storeA(nxt);
                CP_WAIT0();
            }
            __syncthreads();
        }

        // ---- epilogue: stage in smem, plain coalesced stores to scratch ----
#pragma unroll
        for (int j = 0; j < J; ++j) {
            const int col = wn * WN + j * 8 + tg * 2;
#pragma unroll
            for (int i = 0; i < 2; ++i) {
                const int r1 = wm * 32 + i * 16 + g;
                *reinterpret_cast<float2*>(&sAcc[r1 * RSF + col]) =
                    make_float2(acc[i][j][0], acc[i][j][1]);
                *reinterpret_cast<float2*>(&sAcc[(r1 + 8) * RSF + col]) =
                    make_float2(acc[i][j][2], acc[i][j][3]);
            }
        }
        __syncthreads();

        for (int e = t; e < 128 * NQ; e += 256) {
            const int row = e / NQ, q = e - row * NQ;
            const int m = m0 + row;
            const int col0 = n0 + q * 4;
            if (m < cn && col0 < COUT) {
                float4 v = *reinterpret_cast<const float4*>(&sAcc[row * RSF + q * 4]);
                *reinterpret_cast<float4*>(scr + (size_t)(sbase + m) * SSTR + col0) = v;
            }
        }
    }
}

// ---------------------------------------------------------------------------
// Flow conv (K=343, Cin=2, Cout=128): 512 threads, per-warp 4-row tap skip.
// ---------------------------------------------------------------------------
__global__ void __launch_bounds__(512)
flow_conv(const float* __restrict__ flow, const int* __restrict__ nbr7,
          const float* __restrict__ W, const float* __restrict__ bias,
          float* __restrict__ out, int N)
{
    constexpr int KK = 343, BM = 64;
    __shared__ float sF[2][BM * 2];
    __shared__ float sW[2][256];
    __shared__ unsigned char sV[2][BM];

    const int t = threadIdx.x;
    const int warp = t >> 5, lane = t & 31;
    const int row0 = blockIdx.x * BM;

    float acc[4][4];
#pragma unroll
    for (int i = 0; i < 4; ++i)
#pragma unroll
        for (int j = 0; j < 4; ++j) acc[i][j] = 0.f;

    auto load_stage = [&](int k, int buf) {
        if (t < BM) {
            int r = row0 + t;
            int idx = (r < N) ? nbr7[(size_t)k * N + r] : -1;
            float2 v = make_float2(0.f, 0.f);
            if (idx >= 0) v = *reinterpret_cast<const float2*>(&flow[(size_t)idx * 2]);
            sF[buf][t * 2] = v.x;
            sF[buf][t * 2 + 1] = v.y;
            sV[buf][t] = (idx >= 0);
        }
        if (t < 256) sW[buf][t] = W[(size_t)k * 256 + t];
    };

    load_stage(0, 0);
    for (int k = 0; k < KK; ++k) {
        __syncthreads();
        if (k + 1 < KK) load_stage(k + 1, (k + 1) & 1);
        const int buf = k & 1;
        const bool myv = (lane < 4) && (sV[buf][warp * 4 + lane] != 0);
        if (__ballot_sync(0xffffffffu, myv)) {
            const float4 w0 = *reinterpret_cast<const float4*>(&sW[buf][lane * 4]);
            const float4 w1 = *reinterpret_cast<const float4*>(&sW[buf][128 + lane * 4]);
#pragma unroll
            for (int i = 0; i < 4; ++i) {
                const float f0 = sF[buf][(warp * 4 + i) * 2];
                const float f1 = sF[buf][(warp * 4 + i) * 2 + 1];
                acc[i][0] = fmaf(f0, w0.x, fmaf(f1, w1.x, acc[i][0]));
                acc[i][1] = fmaf(f0, w0.y, fmaf(f1, w1.y, acc[i][1]));
                acc[i][2] = fmaf(f0, w0.z, fmaf(f1, w1.z, acc[i][2]));
                acc[i][3] = fmaf(f0, w0.w, fmaf(f1, w1.w, acc[i][3]));
            }
        }
    }

    const float4 bv = *reinterpret_cast<const float4*>(&bias[lane * 4]);
#pragma unroll
    for (int i = 0; i < 4; ++i) {
        const int r = row0 + warp * 4 + i;
        if (r >= N) continue;
        float4 o;
        o.x = fmaxf(acc[i][0] + bv.x, 0.f);
        o.y = fmaxf(acc[i][1] + bv.y, 0.f);
        o.z = fmaxf(acc[i][2] + bv.z, 0.f);
        o.w = fmaxf(acc[i][3] + bv.w, 0.f);
        *reinterpret_cast<float4*>(out + (size_t)r * 128 + lane * 4) = o;
    }
}

__global__ void tail_copy(const float* __restrict__ ext,
                          const float* __restrict__ flow,
                          float* __restrict__ out, int N)
{
    int i = blockIdx.x * blockDim.x + threadIdx.x;
    if (i >= N * 8) return;
    int r = i >> 3, c = i & 7;
    float v = (c < 2) ? flow[(size_t)r * 2 + c] : ext[(size_t)r * 6 + (c - 2)];
    out[(size_t)r * 128 + 120 + c] = v;
}

// ---------------------------------------------------------------------------
extern "C" void kernel_launch(void* const* d_in, const int* in_sizes, int n_in,
                              void* d_out, int out_size)
{
    const float* extr  = (const float*)d_in[0];
    const float* flow  = (const float*)d_in[1];
    const float* corrf = (const float*)d_in[2];
    const int*   nbr3  = (const int*)  d_in[3];
    const int*   nbr7  = (const int*)  d_in[4];
    const float* Wc1   = (const float*)d_in[5];
    const float* bc1   = (const float*)d_in[6];
    const float* Wc2   = (const float*)d_in[7];
    const float* bc2   = (const float*)d_in[8];
    const float* Wf1   = (const float*)d_in[9];
    const float* bf1   = (const float*)d_in[10];
    const float* Wf2   = (const float*)d_in[11];
    const float* bf2   = (const float*)d_in[12];
    const float* Wcat  = (const float*)d_in[13];
    const float* bcat  = (const float*)d_in[14];
    float* out = (float*)d_out;

    const int N = in_sizes[0] / 6;

    float *p_corr1, *p_f1, *p_cat, *p_scrA, *p_scrB;
    cudaGetSymbolAddress((void**)&p_corr1, g_corr1);
    cudaGetSymbolAddress((void**)&p_f1,    g_f1);
    cudaGetSymbolAddress((void**)&p_cat,   g_cat);
    cudaGetSymbolAddress((void**)&p_scrA,  g_scrA);
    cudaGetSymbolAddress((void**)&p_scrB,  g_scrB);
    __nv_bfloat16 *c1h, *c1l, *c2h, *c2l, *f2h, *f2l, *cth, *ctl;
    cudaGetSymbolAddress((void**)&c1h, gW_c1_hi);
    cudaGetSymbolAddress((void**)&c1l, gW_c1_lo);
    cudaGetSymbolAddress((void**)&c2h, gW_c2_hi);
    cudaGetSymbolAddress((void**)&c2l, gW_c2_lo);
    cudaGetSymbolAddress((void**)&f2h, gW_f2_hi);
    cudaGetSymbolAddress((void**)&f2l, gW_f2_lo);
    cudaGetSymbolAddress((void**)&cth, gW_ct_hi);
    cudaGetSymbolAddress((void**)&ctl, gW_ct_lo);

    int nsm = 148;
    cudaDeviceGetAttribute(&nsm, cudaDevAttrMultiProcessorCount, 0);
    const int pgrid = nsm * 2;

    // ---- weight prep + rulebook + CSR ----
    prep_w<1, 324, 256, 352, 256><<<(1 * 256 * 352 + 255) / 256, 256>>>(Wc1, c1h, c1l);
    prep_w<27, 256, 192, 256, 192><<<(27 * 192 * 256 + 255) / 256, 256>>>(Wc2, c2h, c2l);
    prep_w<27, 128, 64, 128, 64><<<(27 * 64 * 128 + 255) / 256, 256>>>(Wf2, f2h, f2l);
    prep_w<27, 256, 120, 256, 128><<<(27 * 128 * 256 + 255) / 256, 256>>>(Wcat, cth, ctl);
    zero_cnt<<<1, 32>>>();
    zero_ccnt<<<(N + 255) / 256, 256>>>(N);
    build_list<<<dim3((N + 255) / 256, 27), 256>>>(nbr3, N);
    sched<<<1, 32>>>();
    build_csr<<<dim3((N + 255) / 256, 27), 256>>>(N);

    const int mblk = (N + 127) / 128;
    auto dsm = [](int NT) { return 4 * 10240 + 4 * NT * 80; };

    cudaFuncSetAttribute(tmma<1, 324, 352, 128>,
                         cudaFuncAttributeMaxDynamicSharedMemorySize, dsm(128));
    cudaFuncSetAttribute(tap_mma_p<256, 256, 96, 2>,
                         cudaFuncAttributeMaxDynamicSharedMemorySize, dsm(96));
    cudaFuncSetAttribute(tap_mma_p<128, 128, 64, 1>,
                         cudaFuncAttributeMaxDynamicSharedMemorySize, dsm(64));
    cudaFuncSetAttribute(tap_mma_p<256, 256, 128, 1>,
                         cudaFuncAttributeMaxDynamicSharedMemorySize, dsm(128));

    // corr1 = relu(corrf @ Wc1 + bc1)  (dense identity)
    tmma<1, 324, 352, 128><<<dim3(mblk, 2), 256, dsm(128)>>>(
        corrf, 324, c1h, c1l, 256, bc1, p_corr1, 256, 0, 256, N);

    // f1 = relu(flow_conv)
    flow_conv<<<(N + 63) / 64, 512>>>(flow, nbr7, Wf1, bf1, p_f1, N);

    // c2 / f2 tap GEMMs -> scratch (no atomics)
    tap_mma_p<256, 256, 96, 2><<<pgrid, 256, dsm(96)>>>(
        p_corr1, 256, c2h, c2l, 192, p_scrA, 192, 192);
    tap_mma_p<128, 128, 64, 1><<<pgrid, 256, dsm(64)>>>(
        p_f1, 128, f2h, f2l, 64, p_scrB, 64, 64);

    // cat = relu(bias + gather-reduce)
    reduce_cat<<<(N + 7) / 8, 256>>>(bc2, bf2, N);

    // final conv -> scratch (stride 128), then reduce to out
    tap_mma_p<256, 256, 128, 1><<<pgrid, 256, dsm(128)>>>(
        p_cat, 256, cth, ctl, 128, p_scrA, 128, 120);
    reduce_out<<<(N + 7) / 8, 256>>>(bcat, out, N);

    tail_copy<<<(N * 8 + 255) / 256, 256>>>(extr, flow, out, N);
}

// round 16
// speedup vs baseline: 1.1148x; 1.1148x over previous
#include <cuda_runtime.h>
#include <cuda_bf16.h>
#include <cstdint>

// ===========================================================================
// SparseMotionEncoder — round 14: R12 (atomic red.v4 epilogue) + stream-level
// parallelism inside graph capture. Fork/join with events turns the two
// independent chains (c1->c2 and flow->f2, plus all prep/init work) into
// concurrent graph branches.
// ===========================================================================

#define NVOX 50000

__device__ float g_corr1[NVOX * 256];
__device__ float g_f1[NVOX * 128];
__device__ float g_cat[NVOX * 256];

__device__ int  g_cnt3[27];
__device__ int2 g_list3[27 * NVOX];     // (in_idx, out_idx) per tap
__device__ int  g_nitems;
__device__ int  g_items[10560];         // packed: tap | (mtile << 5)

// Transposed, split weights: [KK][COUTPAD][CINPAD] bf16, zero padded.
__device__ __nv_bfloat16 gW_c1_hi[1 * 256 * 352], gW_c1_lo[1 * 256 * 352];
__device__ __nv_bfloat16 gW_c2_hi[27 * 192 * 256], gW_c2_lo[27 * 192 * 256];
__device__ __nv_bfloat16 gW_f2_hi[27 * 64 * 128],  gW_f2_lo[27 * 64 * 128];
__device__ __nv_bfloat16 gW_ct_hi[27 * 128 * 256], gW_ct_lo[27 * 128 * 256];

__device__ __forceinline__ uint32_t pkbf(float a, float b) {
    __nv_bfloat162 t = __floats2bfloat162_rn(a, b);
    return *reinterpret_cast<uint32_t*>(&t);
}
__device__ __forceinline__ void mma16816(float* c, const uint32_t* a,
                                         const uint32_t* b) {
    asm volatile(
        "mma.sync.aligned.m16n8k16.row.col.f32.bf16.bf16.f32 "
        "{%0,%1,%2,%3}, {%4,%5,%6,%7}, {%8,%9}, {%0,%1,%2,%3};"
        : "+f"(c[0]), "+f"(c[1]), "+f"(c[2]), "+f"(c[3])
        : "r"(a[0]), "r"(a[1]), "r"(a[2]), "r"(a[3]), "r"(b[0]), "r"(b[1]));
}
__device__ __forceinline__ void ldsm4(uint32_t* r, uint32_t addr) {
    asm volatile(
        "ldmatrix.sync.aligned.m8n8.x4.shared.b16 {%0,%1,%2,%3}, [%4];"
        : "=r"(r[0]), "=r"(r[1]), "=r"(r[2]), "=r"(r[3]) : "r"(addr));
}
__device__ __forceinline__ void cpasync16(uint32_t dst, const void* src) {
    asm volatile("cp.async.cg.shared.global [%0], [%1], 16;" :: "r"(dst), "l"(src));
}
__device__ __forceinline__ void red4(float* p, float4 v) {
    asm volatile("red.global.add.v4.f32 [%0], {%1,%2,%3,%4};"
                 :: "l"(p), "f"(v.x), "f"(v.y), "f"(v.z), "f"(v.w) : "memory");
}
#define CP_COMMIT() asm volatile("cp.async.commit_group;" ::: "memory")
#define CP_WAIT0()  asm volatile("cp.async.wait_group 0;" ::: "memory")

// ---------------------------------------------------------------------------
template <int KK, int CIN, int COUT, int CINPAD, int COUTPAD>
__global__ void prep_w(const float* __restrict__ W,
                       __nv_bfloat16* __restrict__ hi,
                       __nv_bfloat16* __restrict__ lo)
{
    long tid = (long)blockIdx.x * blockDim.x + threadIdx.x;
    const long total = (long)KK * COUTPAD * CINPAD;
    if (tid >= total) return;
    int c = tid % CINPAD;
    long r = tid / CINPAD;
    int n = r % COUTPAD;
    int k = r / COUTPAD;
    float x = (c < CIN && n < COUT) ? W[((size_t)k * CIN + c) * COUT + n] : 0.f;
    __nv_bfloat16 h = __float2bfloat16(x);
    hi[tid] = h;
    lo[tid] = __float2bfloat16(x - __bfloat162float(h));
}

// ---------------------------------------------------------------------------
__global__ void zero_cnt()
{
    if (threadIdx.x < 27) g_cnt3[threadIdx.x] = 0;
    if (threadIdx.x == 31) g_nitems = 0;
}

__global__ void build_list(const int* __restrict__ nbr, int N)
{
    const int k = blockIdx.y;
    const int n = blockIdx.x * 256 + threadIdx.x;
    const int lane = threadIdx.x & 31;
    int idx = -1;
    if (n < N) idx = nbr[(size_t)k * N + n];
    const bool v = idx >= 0;
    unsigned m = __ballot_sync(0xffffffffu, v);
    if (!m) return;
    int leader = __ffs(m) - 1;
    int base = 0;
    if (lane == leader) base = atomicAdd(&g_cnt3[k], __popc(m));
    base = __shfl_sync(0xffffffffu, base, leader);
    if (v) {
        int pos = base + __popc(m & ((1u << lane) - 1u));
        g_list3[(size_t)k * NVOX + pos] = make_int2(idx, n);
    }
}

__global__ void sched()
{
    int k = threadIdx.x;
    if (k < 27) {
        int tiles = (g_cnt3[k] + 127) >> 7;
        int base = atomicAdd(&g_nitems, tiles);
        for (int i = 0; i < tiles; ++i)
            g_items[base + i] = k | (i << 5);
    }
}

// ---------------------------------------------------------------------------
__global__ void init_cat(float* __restrict__ cat,
                         const float* __restrict__ b0,   // 192
                         const float* __restrict__ b1,   // 64
                         int N)
{
    long i = (long)blockIdx.x * blockDim.x + threadIdx.x;
    if (i >= (long)N * 256) return;
    int c = i & 255;
    cat[i] = (c < 192) ? b0[c] : b1[c - 192];
}

__global__ void init_bias(float* __restrict__ out, int ostride, int ocol,
                          const float* __restrict__ bias, int COUT, int N)
{
    long i = (long)blockIdx.x * blockDim.x + threadIdx.x;
    if (i >= (long)N * COUT) return;
    int r = i / COUT, c = i % COUT;
    out[(size_t)r * ostride + ocol + c] = bias[c];
}

__global__ void relu_region(float* __restrict__ p, int stride, int ocol,
                            int COUT, int N)
{
    long i = (long)blockIdx.x * blockDim.x + threadIdx.x;
    if (i >= (long)N * COUT) return;
    int r = i / COUT, c = i % COUT;
    float* q = p + (size_t)r * stride + ocol + c;
    *q = fmaxf(*q, 0.f);
}

// ---------------------------------------------------------------------------
// Dense pipelined HMMA gather-GEMM (identity rows) — c1 only.
// ---------------------------------------------------------------------------
template <int KK, int CIN, int CINPAD, int NT>
__global__ void __launch_bounds__(256, 2)
tmma(const float* __restrict__ feat, int fstride,
     const __nv_bfloat16* __restrict__ Whi, const __nv_bfloat16* __restrict__ Wlo,
     int COUTPAD, const float* __restrict__ bias, float* __restrict__ out,
     int ostride, int ocol, int COUT, int N)
{
    constexpr bool TAIL = (CIN % 32) != 0;
    constexpr int CH = CINPAD / 32;
    constexpr int ITERS = KK * CH;
    constexpr int WN = NT / 2;
    constexpr int J  = NT / 16;
    constexpr int JP = J / 2;
    constexpr int BQ = (NT * 8) / 256;
    constexpr uint32_t AB = 10240;
    constexpr uint32_t BB = NT * 80;

    extern __shared__ char dyn[];
    const uint32_t sb = (uint32_t)__cvta_generic_to_shared(dyn);

    const int t = threadIdx.x, lane = t & 31, w = t >> 5;
    const int wm = w >> 1, wn = w & 1;
    const int g = lane >> 2, tg = lane & 3;
    const int row0 = blockIdx.x * 128;
    const int n0 = blockIdx.y * NT;

    float acc[2][J][4];
#pragma unroll
    for (int i = 0; i < 2; ++i)
#pragma unroll
        for (int j = 0; j < J; ++j)
#pragma unroll
            for (int q = 0; q < 4; ++q) acc[i][j][q] = 0.f;

    const int gr = t >> 1;
    const int gcb = (t & 1) * 16;
    const int grow = row0 + gr;

    float4 va[4];

    auto gatherA = [&](int it) {
        const int cc = it % CH;
        const float* frow = (grow < N) ? feat + (size_t)grow * fstride : nullptr;
        const int c0 = cc * 32;
#pragma unroll
        for (int i = 0; i < 4; ++i) {
            const int gcol = c0 + gcb + i * 4;
            float4 v = make_float4(0.f, 0.f, 0.f, 0.f);
            if (frow) {
                if (!TAIL || gcol + 3 < CIN) {
                    v = *reinterpret_cast<const float4*>(frow + gcol);
                } else {
                    float tmp[4] = {0.f, 0.f, 0.f, 0.f};
#pragma unroll
                    for (int jj = 0; jj < 4; ++jj)
                        if (gcol + jj < CIN) tmp[jj] = frow[gcol + jj];
                    v = make_float4(tmp[0], tmp[1], tmp[2], tmp[3]);
                }
            }
            va[i] = v;
        }
    };

    auto storeA = [&](int stage) {
        char* base_h = dyn + (stage * 2 + 0) * AB;
        char* base_l = dyn + (stage * 2 + 1) * AB;
        const int roff = gr * 80;
#pragma unroll
        for (int i = 0; i < 4; ++i) {
            float4 v = va[i];
            float hx = __bfloat162float(__float2bfloat16(v.x));
            float hy = __bfloat162float(__float2bfloat16(v.y));
            float hz = __bfloat162float(__float2bfloat16(v.z));
            float hw = __bfloat162float(__float2bfloat16(v.w));
            uint2 uh = make_uint2(pkbf(hx, hy), pkbf(hz, hw));
            uint2 ul = make_uint2(pkbf(v.x - hx, v.y - hy),
                                  pkbf(v.z - hz, v.w - hw));
            const int boff = roff + (gcb + i * 4) * 2;
            *reinterpret_cast<uint2*>(base_h + boff) = uh;
            *reinterpret_cast<uint2*>(base_l + boff) = ul;
        }
    };

    auto issueB = [&](int it, int stage) {
        const int k = it / CH, cc = it % CH;
        const size_t base = ((size_t)k * COUTPAD + n0) * CINPAD + cc * 32;
#pragma unroll
        for (int q = 0; q < BQ; ++q) {
            const int e = t + q * 256;
            const int plane = e / (NT * 4);
            const int re = e - plane * (NT * 4);
            const int row = re >> 2, seg = re & 3;
            const __nv_bfloat16* src =
                (plane ? Wlo : Whi) + base + (size_t)row * CINPAD + seg * 8;
            const uint32_t dst =
                sb + 4 * AB + (uint32_t)(stage * 2 + plane) * BB + row * 80 + seg * 16;
            cpasync16(dst, src);
        }
    };

    gatherA(0);
    issueB(0, 0);
    CP_COMMIT();
    storeA(0);
    CP_WAIT0();
    __syncthreads();

    const int local = lane & 7, grp = lane >> 3;
    const int arow = (grp & 1) * 8 + local;
    const int abyt = (grp >> 1) * 16;
    const int nloc = (grp >> 1) * 8 + local;
    const int bbyt = (grp & 1) * 16;

#pragma unroll 1
    for (int it = 0; it < ITERS; ++it) {
        const int cur = it & 1, nxt = cur ^ 1;
        const bool more = (it + 1 < ITERS);
        if (more) {
            gatherA(it + 1);
            issueB(it + 1, nxt);
            CP_COMMIT();
        }
        const uint32_t aH = sb + (uint32_t)(cur * 2 + 0) * AB;
        const uint32_t aL = sb + (uint32_t)(cur * 2 + 1) * AB;
        const uint32_t bH = sb + 4 * AB + (uint32_t)(cur * 2 + 0) * BB;
        const uint32_t bL = sb + 4 * AB + (uint32_t)(cur * 2 + 1) * BB;
#pragma unroll
        for (int ks = 0; ks < 2; ++ks) {
            uint32_t Ah[2][4], Al[2][4];
#pragma unroll
            for (int i = 0; i < 2; ++i) {
                const uint32_t ao =
                    (uint32_t)((wm * 32 + i * 16 + arow) * 80 + ks * 32 + abyt);
                ldsm4(Ah[i], aH + ao);
                ldsm4(Al[i], aL + ao);
            }
#pragma unroll
            for (int jp = 0; jp < JP; ++jp) {
                const uint32_t bo =
                    (uint32_t)((wn * WN + jp * 16 + nloc) * 80 + ks * 32 + bbyt);
                uint32_t Bh[4], Bl[4];
                ldsm4(Bh, bH + bo);
                ldsm4(Bl, bL + bo);
#pragma unroll
                for (int i = 0; i < 2; ++i) {
                    mma16816(acc[i][2 * jp],     Ah[i], Bh);
                    mma16816(acc[i][2 * jp],     Al[i], Bh);
                    mma16816(acc[i][2 * jp],     Ah[i], Bl);
                    mma16816(acc[i][2 * jp + 1], Ah[i], Bh + 2);
                    mma16816(acc[i][2 * jp + 1], Al[i], Bh + 2);
                    mma16816(acc[i][2 * jp + 1], Ah[i], Bl + 2);
                }
            }
        }
        if (more) {
            storeA(nxt);
            CP_WAIT0();
        }
        __syncthreads();
    }

#pragma unroll
    for (int j = 0; j < J; ++j) {
        const int col = n0 + wn * WN + j * 8 + tg * 2;
        if (col >= COUT) continue;
        const float2 bv = *reinterpret_cast<const float2*>(bias + col);
#pragma unroll
        for (int i = 0; i < 2; ++i) {
            const int r1 = row0 + wm * 32 + i * 16 + g;
            if (r1 < N) {
                float2 o = make_float2(fmaxf(acc[i][j][0] + bv.x, 0.f),
                                       fmaxf(acc[i][j][1] + bv.y, 0.f));
                *reinterpret_cast<float2*>(out + (size_t)r1 * ostride + ocol + col) = o;
            }
            const int r2 = r1 + 8;
            if (r2 < N) {
                float2 o = make_float2(fmaxf(acc[i][j][2] + bv.x, 0.f),
                                       fmaxf(acc[i][j][3] + bv.y, 0.f));
                *reinterpret_cast<float2*>(out + (size_t)r2 * ostride + ocol + col) = o;
            }
        }
    }
}

// ---------------------------------------------------------------------------
// Persistent per-tap rulebook HMMA GEMM. Grid-stride over device-built work
// items (tap, mtile) x NYT n-tiles. Epilogue: stage acc tile in smem, then
// coalesced red.global.add.v4.f32.
// ---------------------------------------------------------------------------
template <int CIN, int CINPAD, int NT, int NYT, bool RELUIN>
__global__ void __launch_bounds__(256, 2)
tap_mma_p(const float* __restrict__ feat, int fstride,
          const __nv_bfloat16* __restrict__ Whi, const __nv_bfloat16* __restrict__ Wlo,
          int COUTPAD, float* __restrict__ out, int ostride, int ocol, int COUT)
{
    constexpr int CH = CINPAD / 32;
    constexpr int WN = NT / 2;
    constexpr int J  = NT / 16;
    constexpr int JP = J / 2;
    constexpr int BQ = (NT * 8) / 256;
    constexpr uint32_t AB = 10240;
    constexpr uint32_t BB = NT * 80;
    constexpr int RSF = NT + 4;          // acc stage row stride (floats)
    constexpr int NQ = NT / 4;

    __shared__ int sIn[128], sOut[128];
    extern __shared__ char dyn[];
    const uint32_t sb = (uint32_t)__cvta_generic_to_shared(dyn);
    float* sAcc = reinterpret_cast<float*>(dyn);

    const int t = threadIdx.x, lane = t & 31, w = t >> 5;
    const int wm = w >> 1, wn = w & 1;
    const int g = lane >> 2, tg = lane & 3;
    const int gr = t >> 1;
    const int gcb = (t & 1) * 16;
    const int local = lane & 7, grp = lane >> 3;
    const int arow = (grp & 1) * 8 + local;
    const int abyt = (grp >> 1) * 16;
    const int nloc = (grp >> 1) * 8 + local;
    const int bbyt = (grp & 1) * 16;

    const int nwork = g_nitems * NYT;

    for (int wk = blockIdx.x; wk < nwork; wk += gridDim.x) {
        const int item = (NYT == 1) ? wk : (wk >> 1);
        const int y    = (NYT == 1) ? 0  : (wk & 1);
        const int packed = g_items[item];
        const int tap = packed & 31;
        const int m0 = (packed >> 5) << 7;
        const int cn = g_cnt3[tap];
        const int n0 = y * NT;

        __syncthreads();   // prior epilogue's smem reads done
        if (t < 128) {
            const int m = m0 + t;
            if (m < cn) {
                int2 p = g_list3[(size_t)tap * NVOX + m];
                sIn[t] = p.x;
                sOut[t] = p.y;
            } else {
                sIn[t] = -1;
                sOut[t] = -1;
            }
        }
        __syncthreads();

        float acc[2][J][4];
#pragma unroll
        for (int i = 0; i < 2; ++i)
#pragma unroll
            for (int j = 0; j < J; ++j)
#pragma unroll
                for (int q = 0; q < 4; ++q) acc[i][j][q] = 0.f;

        const int gin = sIn[gr];
        const float* frow = (gin >= 0) ? feat + (size_t)gin * fstride : nullptr;

        float4 va[4];
        auto gatherA = [&](int it) {
            const int c0 = it * 32;
#pragma unroll
            for (int i = 0; i < 4; ++i) {
                float4 v = make_float4(0.f, 0.f, 0.f, 0.f);
                if (frow) {
                    v = *reinterpret_cast<const float4*>(frow + c0 + gcb + i * 4);
                    if (RELUIN) {
                        v.x = fmaxf(v.x, 0.f);
                        v.y = fmaxf(v.y, 0.f);
                        v.z = fmaxf(v.z, 0.f);
                        v.w = fmaxf(v.w, 0.f);
                    }
                }
                va[i] = v;
            }
        };
        auto storeA = [&](int stage) {
            char* base_h = dyn + (stage * 2 + 0) * AB;
            char* base_l = dyn + (stage * 2 + 1) * AB;
            const int roff = gr * 80;
#pragma unroll
            for (int i = 0; i < 4; ++i) {
                float4 v = va[i];
                float hx = __bfloat162float(__float2bfloat16(v.x));
                float hy = __bfloat162float(__float2bfloat16(v.y));
                float hz = __bfloat162float(__float2bfloat16(v.z));
                float hw = __bfloat162float(__float2bfloat16(v.w));
                uint2 uh = make_uint2(pkbf(hx, hy), pkbf(hz, hw));
                uint2 ul = make_uint2(pkbf(v.x - hx, v.y - hy),
                                      pkbf(v.z - hz, v.w - hw));
                const int boff = roff + (gcb + i * 4) * 2;
                *reinterpret_cast<uint2*>(base_h + boff) = uh;
                *reinterpret_cast<uint2*>(base_l + boff) = ul;
            }
        };
        auto issueB = [&](int it, int stage) {
            const size_t base = ((size_t)tap * COUTPAD + n0) * CINPAD + it * 32;
#pragma unroll
            for (int q = 0; q < BQ; ++q) {
                const int e = t + q * 256;
                const int plane = e / (NT * 4);
                const int re = e - plane * (NT * 4);
                const int row = re >> 2, seg = re & 3;
                const __nv_bfloat16* src =
                    (plane ? Wlo : Whi) + base + (size_t)row * CINPAD + seg * 8;
                const uint32_t dst =
                    sb + 4 * AB + (uint32_t)(stage * 2 + plane) * BB + row * 80 + seg * 16;
                cpasync16(dst, src);
            }
        };

        gatherA(0);
        issueB(0, 0);
        CP_COMMIT();
        storeA(0);
        CP_WAIT0();
        __syncthreads();

#pragma unroll 1
        for (int it = 0; it < CH; ++it) {
            const int cur = it & 1, nxt = cur ^ 1;
            const bool more = (it + 1 < CH);
            if (more) {
                gatherA(it + 1);
                issueB(it + 1, nxt);
                CP_COMMIT();
            }
            const uint32_t aH = sb + (uint32_t)(cur * 2 + 0) * AB;
            const uint32_t aL = sb + (uint32_t)(cur * 2 + 1) * AB;
            const uint32_t bH = sb + 4 * AB + (uint32_t)(cur * 2 + 0) * BB;
            const uint32_t bL = sb + 4 * AB + (uint32_t)(cur * 2 + 1) * BB;
#pragma unroll
            for (int ks = 0; ks < 2; ++ks) {
                uint32_t Ah[2][4], Al[2][4];
#pragma unroll
                for (int i = 0; i < 2; ++i) {
                    const uint32_t ao =
                        (uint32_t)((wm * 32 + i * 16 + arow) * 80 + ks * 32 + abyt);
                    ldsm4(Ah[i], aH + ao);
                    ldsm4(Al[i], aL + ao);
                }
#pragma unroll
                for (int jp = 0; jp < JP; ++jp) {
                    const uint32_t bo =
                        (uint32_t)((wn * WN + jp * 16 + nloc) * 80 + ks * 32 + bbyt);
                    uint32_t Bh[4], Bl[4];
                    ldsm4(Bh, bH + bo);
                    ldsm4(Bl, bL + bo);
#pragma unroll
                    for (int i = 0; i < 2; ++i) {
                        mma16816(acc[i][2 * jp],     Ah[i], Bh);
                        mma16816(acc[i][2 * jp],     Al[i], Bh);
                        mma16816(acc[i][2 * jp],     Ah[i], Bl);
                        mma16816(acc[i][2 * jp + 1], Ah[i], Bh + 2);
                        mma16816(acc[i][2 * jp + 1], Al[i], Bh + 2);
                        mma16816(acc[i][2 * jp + 1], Ah[i], Bl + 2);
                    }
                }
            }
            if (more) {
                storeA(nxt);
                CP_WAIT0();
            }
            __syncthreads();
        }

        // ---- epilogue: stage acc tile in smem, coalesced v4 reductions ----
#pragma unroll
        for (int j = 0; j < J; ++j) {
            const int col = wn * WN + j * 8 + tg * 2;
#pragma unroll
            for (int i = 0; i < 2; ++i) {
                const int r1 = wm * 32 + i * 16 + g;
                *reinterpret_cast<float2*>(&sAcc[r1 * RSF + col]) =
                    make_float2(acc[i][j][0], acc[i][j][1]);
                *reinterpret_cast<float2*>(&sAcc[(r1 + 8) * RSF + col]) =
                    make_float2(acc[i][j][2], acc[i][j][3]);
            }
        }
        __syncthreads();

        for (int e = t; e < 128 * NQ; e += 256) {
            const int row = e / NQ, q = e - row * NQ;
            const int ro = sOut[row];
            const int col0 = n0 + q * 4;
            if (ro >= 0 && col0 < COUT) {
                float4 v = *reinterpret_cast<const float4*>(&sAcc[row * RSF + q * 4]);
                red4(out + (size_t)ro * ostride + ocol + col0, v);
            }
        }
    }
}

// ---------------------------------------------------------------------------
// Flow conv (K=343, Cin=2, Cout=128): 512 threads, per-warp 4-row tap skip.
// ---------------------------------------------------------------------------
__global__ void __launch_bounds__(512)
flow_conv(const float* __restrict__ flow, const int* __restrict__ nbr7,
          const float* __restrict__ W, const float* __restrict__ bias,
          float* __restrict__ out, int N)
{
    constexpr int KK = 343, BM = 64;
    __shared__ float sF[2][BM * 2];
    __shared__ float sW[2][256];
    __shared__ unsigned char sV[2][BM];

    const int t = threadIdx.x;
    const int warp = t >> 5, lane = t & 31;
    const int row0 = blockIdx.x * BM;

    float acc[4][4];
#pragma unroll
    for (int i = 0; i < 4; ++i)
#pragma unroll
        for (int j = 0; j < 4; ++j) acc[i][j] = 0.f;

    auto load_stage = [&](int k, int buf) {
        if (t < BM) {
            int r = row0 + t;
            int idx = (r < N) ? nbr7[(size_t)k * N + r] : -1;
            float2 v = make_float2(0.f, 0.f);
            if (idx >= 0) v = *reinterpret_cast<const float2*>(&flow[(size_t)idx * 2]);
            sF[buf][t * 2] = v.x;
            sF[buf][t * 2 + 1] = v.y;
            sV[buf][t] = (idx >= 0);
        }
        if (t < 256) sW[buf][t] = W[(size_t)k * 256 + t];
    };

    load_stage(0, 0);
    for (int k = 0; k < KK; ++k) {
        __syncthreads();
        if (k + 1 < KK) load_stage(k + 1, (k + 1) & 1);
        const int buf = k & 1;
        const bool myv = (lane < 4) && (sV[buf][warp * 4 + lane] != 0);
        if (__ballot_sync(0xffffffffu, myv)) {
            const float4 w0 = *reinterpret_cast<const float4*>(&sW[buf][lane * 4]);
            const float4 w1 = *reinterpret_cast<const float4*>(&sW[buf][128 + lane * 4]);
#pragma unroll
            for (int i = 0; i < 4; ++i) {
                const float f0 = sF[buf][(warp * 4 + i) * 2];
                const float f1 = sF[buf][(warp * 4 + i) * 2 + 1];
                acc[i][0] = fmaf(f0, w0.x, fmaf(f1, w1.x, acc[i][0]));
                acc[i][1] = fmaf(f0, w0.y, fmaf(f1, w1.y, acc[i][1]));
                acc[i][2] = fmaf(f0, w0.z, fmaf(f1, w1.z, acc[i][2]));
                acc[i][3] = fmaf(f0, w0.w, fmaf(f1, w1.w, acc[i][3]));
            }
        }
    }

    const float4 bv = *reinterpret_cast<const float4*>(&bias[lane * 4]);
#pragma unroll
    for (int i = 0; i < 4; ++i) {
        const int r = row0 + warp * 4 + i;
        if (r >= N) continue;
        float4 o;
        o.x = fmaxf(acc[i][0] + bv.x, 0.f);
        o.y = fmaxf(acc[i][1] + bv.y, 0.f);
        o.z = fmaxf(acc[i][2] + bv.z, 0.f);
        o.w = fmaxf(acc[i][3] + bv.w, 0.f);
        *reinterpret_cast<float4*>(out + (size_t)r * 128 + lane * 4) = o;
    }
}

__global__ void tail_copy(const float* __restrict__ ext,
                          const float* __restrict__ flow,
                          float* __restrict__ out, int N)
{
    int i = blockIdx.x * blockDim.x + threadIdx.x;
    if (i >= N * 8) return;
    int r = i >> 3, c = i & 7;
    float v = (c < 2) ? flow[(size_t)r * 2 + c] : ext[(size_t)r * 6 + (c - 2)];
    out[(size_t)r * 128 + 120 + c] = v;
}

// ---------------------------------------------------------------------------
extern "C" void kernel_launch(void* const* d_in, const int* in_sizes, int n_in,
                              void* d_out, int out_size)
{
    const float* extr  = (const float*)d_in[0];
    const float* flow  = (const float*)d_in[1];
    const float* corrf = (const float*)d_in[2];
    const int*   nbr3  = (const int*)  d_in[3];
    const int*   nbr7  = (const int*)  d_in[4];
    const float* Wc1   = (const float*)d_in[5];
    const float* bc1   = (const float*)d_in[6];
    const float* Wc2   = (const float*)d_in[7];
    const float* bc2   = (const float*)d_in[8];
    const float* Wf1   = (const float*)d_in[9];
    const float* bf1   = (const float*)d_in[10];
    const float* Wf2   = (const float*)d_in[11];
    const float* bf2   = (const float*)d_in[12];
    const float* Wcat  = (const float*)d_in[13];
    const float* bcat  = (const float*)d_in[14];
    float* out = (float*)d_out;

    const int N = in_sizes[0] / 6;

    float *p_corr1, *p_f1, *p_cat;
    cudaGetSymbolAddress((void**)&p_corr1, g_corr1);
    cudaGetSymbolAddress((void**)&p_f1,    g_f1);
    cudaGetSymbolAddress((void**)&p_cat,   g_cat);
    __nv_bfloat16 *c1h, *c1l, *c2h, *c2l, *f2h, *f2l, *cth, *ctl;
    cudaGetSymbolAddress((void**)&c1h, gW_c1_hi);
    cudaGetSymbolAddress((void**)&c1l, gW_c1_lo);
    cudaGetSymbolAddress((void**)&c2h, gW_c2_hi);
    cudaGetSymbolAddress((void**)&c2l, gW_c2_lo);
    cudaGetSymbolAddress((void**)&f2h, gW_f2_hi);
    cudaGetSymbolAddress((void**)&f2l, gW_f2_lo);
    cudaGetSymbolAddress((void**)&cth, gW_ct_hi);
    cudaGetSymbolAddress((void**)&ctl, gW_ct_lo);

    int nsm = 148;
    cudaDeviceGetAttribute(&nsm, cudaDevAttrMultiProcessorCount, 0);
    const int pgrid = nsm * 2;

    // One-time stream/event setup (host resources; no device memory).
    static cudaStream_t s1 = nullptr, s2 = nullptr;
    static cudaEvent_t evFork = nullptr, evRB = nullptr, evF2 = nullptr;
    if (!s1) {
        cudaStreamCreateWithFlags(&s1, cudaStreamNonBlocking);
        cudaStreamCreateWithFlags(&s2, cudaStreamNonBlocking);
        cudaEventCreateWithFlags(&evFork, cudaEventDisableTiming);
        cudaEventCreateWithFlags(&evRB,   cudaEventDisableTiming);
        cudaEventCreateWithFlags(&evF2,   cudaEventDisableTiming);
    }

    const int mblk = (N + 127) / 128;
    auto dsm = [](int NT) { return 4 * 10240 + 4 * NT * 80; };

    cudaFuncSetAttribute(tmma<1, 324, 352, 128>,
                         cudaFuncAttributeMaxDynamicSharedMemorySize, dsm(128));
    cudaFuncSetAttribute(tap_mma_p<256, 256, 96, 2, false>,
                         cudaFuncAttributeMaxDynamicSharedMemorySize, dsm(96));
    cudaFuncSetAttribute(tap_mma_p<128, 128, 64, 1, false>,
                         cudaFuncAttributeMaxDynamicSharedMemorySize, dsm(64));
    cudaFuncSetAttribute(tap_mma_p<256, 256, 128, 1, true>,
                         cudaFuncAttributeMaxDynamicSharedMemorySize, dsm(128));

    // ---- fork side streams off the (captured) legacy stream ----
    cudaEventRecord(evFork, 0);
    cudaStreamWaitEvent(s1, evFork, 0);
    cudaStreamWaitEvent(s2, evFork, 0);

    // ---- main stream: c1 chain ----
    prep_w<1, 324, 256, 352, 256><<<(1 * 256 * 352 + 255) / 256, 256>>>(Wc1, c1h, c1l);
    tmma<1, 324, 352, 128><<<dim3(mblk, 2), 256, dsm(128)>>>(
        corrf, 324, c1h, c1l, 256, bc1, p_corr1, 256, 0, 256, N);

    // ---- s1: rulebook + c2 weights + cat bias init ----
    zero_cnt<<<1, 32, 0, s1>>>();
    build_list<<<dim3((N + 255) / 256, 27), 256, 0, s1>>>(nbr3, N);
    sched<<<1, 32, 0, s1>>>();
    prep_w<27, 256, 192, 256, 192><<<(27 * 192 * 256 + 255) / 256, 256, 0, s1>>>(Wc2, c2h, c2l);
    init_cat<<<((long)N * 256 + 255) / 256, 256, 0, s1>>>(p_cat, bc2, bf2, N);
    cudaEventRecord(evRB, s1);

    // ---- s2: flow chain + misc prep + f2 ----
    flow_conv<<<(N + 63) / 64, 512, 0, s2>>>(flow, nbr7, Wf1, bf1, p_f1, N);
    prep_w<27, 128, 64, 128, 64><<<(27 * 64 * 128 + 255) / 256, 256, 0, s2>>>(Wf2, f2h, f2l);
    prep_w<27, 256, 120, 256, 128><<<(27 * 128 * 256 + 255) / 256, 256, 0, s2>>>(Wcat, cth, ctl);
    init_bias<<<((long)N * 120 + 255) / 256, 256, 0, s2>>>(out, 128, 0, bcat, 120, N);
    tail_copy<<<(N * 8 + 255) / 256, 256, 0, s2>>>(extr, flow, out, N);
    cudaStreamWaitEvent(s2, evRB, 0);      // needs rulebook + init_cat
    tap_mma_p<128, 128, 64, 1, false><<<pgrid, 256, dsm(64), s2>>>(
        p_f1, 128, f2h, f2l, 64, p_cat, 256, 192, 64);
    cudaEventRecord(evF2, s2);

    // ---- main: c2 (needs rulebook + init_cat + c1) ----
    cudaStreamWaitEvent(0, evRB, 0);
    tap_mma_p<256, 256, 96, 2, false><<<pgrid, 256, dsm(96)>>>(
        p_corr1, 256, c2h, c2l, 192, p_cat, 256, 0, 192);

    // ---- main: final conv (needs c2 [stream order], f2/prep_ct/init_bias/tail [evF2]) ----
    cudaStreamWaitEvent(0, evF2, 0);
    tap_mma_p<256, 256, 128, 1, true><<<pgrid, 256, dsm(128)>>>(
        p_cat, 256, cth, ctl, 128, out, 128, 0, 120);
    relu_region<<<((long)N * 120 + 255) / 256, 256>>>(out, 128, 0, 120, N);
}